// round 16
// baseline (speedup 1.0000x reference)
#include <cuda_runtime.h>
#include <cuda_bf16.h>
#include <math.h>
#include <stdint.h>

// ---------------- problem constants ----------------
#define NB     32
#define NFEAT  64
#define NH     256
#define NP     96
#define TM     32           // rows per tile
#define NT     256          // 8 warps per CTA; 2 CTAs per SM
#define PS     100          // padded row stride (floats) for pp

#define TWO_PI_F   6.2831853071795864769f
#define MIN_WH     1e-3f
#define MIN_D      1e-3f
#define DERIV_OFF  0.5413248546129181f     // log(e-1)
#define SIZE_SCALE (1.0f - 1e-3f * 32.0f)

// ---- smem layout (bytes), per CTA = 112.5 KB -> 2 CTAs/SM ----
#define SM_W1H   0          // W1T hi [256 n][64 k bf16 = 128B rows, SWZ128]  32KB
#define SM_W1L   32768
#define SM_HH    65536      // h hi [32 r][256 bf16, SWZ512]                  16KB
#define SM_HL    81920      // h lo                                           16KB
#define SM_PP    98304      // spline params f32[32][PS] (own buffer)       12.8KB
#define SM_B1    111104     // b1 f32[256]
#define SM_B2    112128     // b2 f32[96]
#define SM_TOTAL 112512

#define SWZ128(o) ((uint32_t)(o) ^ (((uint32_t)(o) >> 3) & 0x70u))
#define SWZ512(o) ((uint32_t)(o) ^ (((uint32_t)(o) >> 5) & 0x70u))

// ---------------- pre-split weights (device globals) ----------------
__device__ uint32_t g_W1T_hi[NH * NFEAT / 2];   // [n][kpair]
__device__ uint32_t g_W1T_lo[NH * NFEAT / 2];
// W2 fragment-ordered: [ng(4)][k(16)][n(3)][lane(32)] -> uint4{bh0,bh1,bl0,bl1}
__device__ uint4 g_W2F[4 * 16 * 3 * 32];

// ---------------- helpers ----------------
static __device__ __forceinline__ uint32_t smem_u32(const void* p) {
    uint32_t a;
    asm("{ .reg .u64 t; cvta.to.shared.u64 t, %1; cvt.u32.u64 %0, t; }" : "=r"(a) : "l"(p));
    return a;
}
static __device__ __forceinline__ void ldsm_x4(uint32_t addr, uint32_t r[4]) {
    asm volatile("ldmatrix.sync.aligned.m8n8.x4.shared.b16 {%0,%1,%2,%3}, [%4];"
                 : "=r"(r[0]), "=r"(r[1]), "=r"(r[2]), "=r"(r[3]) : "r"(addr));
}
static __device__ __forceinline__ void mma16816(float c[4], const uint32_t a[4],
                                                uint32_t b0, uint32_t b1) {
    asm volatile("mma.sync.aligned.m16n8k16.row.col.f32.bf16.bf16.f32 "
                 "{%0,%1,%2,%3}, {%4,%5,%6,%7}, {%8,%9}, {%0,%1,%2,%3};"
                 : "+f"(c[0]), "+f"(c[1]), "+f"(c[2]), "+f"(c[3])
                 : "r"(a[0]), "r"(a[1]), "r"(a[2]), "r"(a[3]), "r"(b0), "r"(b1));
}
static __device__ __forceinline__ uint32_t pack_hi(float v0, float v1) {
    __nv_bfloat16 h0 = __float2bfloat16_rn(v0), h1 = __float2bfloat16_rn(v1);
    return (uint32_t)__bfloat16_as_ushort(h0) | ((uint32_t)__bfloat16_as_ushort(h1) << 16);
}
static __device__ __forceinline__ uint32_t pack_lo(float v0, float v1) {
    __nv_bfloat16 h0 = __float2bfloat16_rn(v0), h1 = __float2bfloat16_rn(v1);
    __nv_bfloat16 l0 = __float2bfloat16_rn(v0 - __bfloat162float(h0));
    __nv_bfloat16 l1 = __float2bfloat16_rn(v1 - __bfloat162float(h1));
    return (uint32_t)__bfloat16_as_ushort(l0) | ((uint32_t)__bfloat16_as_ushort(l1) << 16);
}
static __device__ __forceinline__ float softplus_f(float x) {
    return (x > 0.0f) ? (x + __logf(1.0f + __expf(-x))) : __logf(1.0f + __expf(x));
}

// 4-row interleaved circular RQ spline (lane = bin); rows rr = w + 8j
static __device__ __forceinline__ void spline_rows4(const float* pp, int w, int l,
                                                    int row0,
                                                    const float* __restrict__ theta,
                                                    float* __restrict__ out, int B)
{
    const unsigned FULL = 0xffffffffu;
    float uw[4], uh[4], ud[4], thv[4];
    int rowv[4];
    #pragma unroll
    for (int j = 0; j < 4; j++) {
        int rr = w + 8 * j;
        int row = row0 + rr;
        rowv[j] = row;
        thv[j] = (row < B) ? theta[row] : 0.f;
        uw[j] = pp[rr * PS + l];
        uh[j] = pp[rr * PS + NB + l];
        ud[j] = pp[rr * PS + 2 * NB + l] + DERIV_OFF;
    }

    float cw[4], ch[4];
    #pragma unroll
    for (int j = 0; j < 4; j++) { cw[j] = __expf(uw[j]); ch[j] = __expf(uh[j]); }

    #pragma unroll
    for (int o = 1; o < 32; o <<= 1) {
        float aw[4], ah[4];
        #pragma unroll
        for (int j = 0; j < 4; j++) {
            aw[j] = __shfl_up_sync(FULL, cw[j], o);
            ah[j] = __shfl_up_sync(FULL, ch[j], o);
        }
        #pragma unroll
        for (int j = 0; j < 4; j++) {
            if (l >= o) { cw[j] += aw[j]; ch[j] += ah[j]; }
        }
    }

    float kw[4], kh[4], dsp[4];
    const float base = MIN_WH * (float)(l + 1);
    #pragma unroll
    for (int j = 0; j < 4; j++) {
        float rw = 1.0f / __shfl_sync(FULL, cw[j], 31);
        float rh = 1.0f / __shfl_sync(FULL, ch[j], 31);
        kw[j] = (l == 31) ? TWO_PI_F : TWO_PI_F * (base + SIZE_SCALE * cw[j] * rw);
        kh[j] = (l == 31) ? TWO_PI_F : TWO_PI_F * (base + SIZE_SCALE * ch[j] * rh);
        dsp[j] = MIN_D + softplus_f(ud[j]);
    }

    #pragma unroll
    for (int j = 0; j < 4; j++) {
        unsigned bal = __ballot_sync(FULL, thv[j] >= kw[j]);
        int bin = __popc(bal);
        if (bin > NB - 1) bin = NB - 1;
        int lo = (bin > 0) ? bin - 1 : 0;

        float cw_hi = __shfl_sync(FULL, kw[j], bin);
        float cw_lo = __shfl_sync(FULL, kw[j], lo);
        float ch_hi = __shfl_sync(FULL, kh[j], bin);
        float ch_lo = __shfl_sync(FULL, kh[j], lo);
        float d_k   = __shfl_sync(FULL, dsp[j], bin);
        float d_k1  = __shfl_sync(FULL, dsp[j], (bin + 1) & 31);
        if (bin == 0) { cw_lo = 0.0f; ch_lo = 0.0f; }

        float in_w = cw_hi - cw_lo;
        float in_h = ch_hi - ch_lo;

        float delta = in_h / in_w;
        float th    = (thv[j] - cw_lo) / in_w;
        float om    = th * (1.0f - th);
        float den   = delta + (d_k1 + d_k - 2.0f * delta) * om;
        float num   = in_h * (delta * th * th + d_k * om);
        float outv  = ch_lo + num / den;

        float omt = 1.0f - th;
        float dn  = delta * delta * (d_k1 * th * th + 2.0f * delta * om + d_k * omt * omt);
        float lad = __logf(dn) - 2.0f * __logf(den);

        if (l == 0 && rowv[j] < B) {
            out[rowv[j]]     = outv;
            out[B + rowv[j]] = lad;
        }
    }
}

// ---------------- prep: W1T hi/lo pairs + W2 fragment-ordered uint4 ----------------
__global__ void prep_kernel(const float* __restrict__ W1, const float* __restrict__ W2)
{
    int i = blockIdx.x * blockDim.x + threadIdx.x;
    if (i < NH * NFEAT / 2) {                      // W1 [64][256] -> W1T[n][kpair]
        int n = i >> 5, kp = i & 31;
        float w0 = W1[(2 * kp)     * NH + n];
        float w1 = W1[(2 * kp + 1) * NH + n];
        g_W1T_hi[i] = pack_hi(w0, w1);
        g_W1T_lo[i] = pack_lo(w0, w1);
    }
    int j = i - NH * NFEAT / 2;
    if (j >= 0 && j < 4 * 16 * 3 * 32) {           // W2F fragment layout
        int ng   = j / (16 * 3 * 32);
        int rem  = j - ng * (16 * 3 * 32);
        int k    = rem / (3 * 32);
        int n    = (rem / 32) % 3;
        int lane = rem & 31;

        int n2  = ng * 24 + n * 8 + (lane >> 2);
        int kp0 = k * 8 + (lane & 3);
        int kp1 = kp0 + 4;
        float a0 = W2[(2 * kp0)     * NP + n2];
        float a1 = W2[(2 * kp0 + 1) * NP + n2];
        float b0 = W2[(2 * kp1)     * NP + n2];
        float b1 = W2[(2 * kp1 + 1) * NP + n2];
        uint4 v;
        v.x = pack_hi(a0, a1);
        v.y = pack_hi(b0, b1);
        v.z = pack_lo(a0, a1);
        v.w = pack_lo(b0, b1);
        g_W2F[j] = v;
    }
}

// ---------------- persistent fused kernel: 8 warps/CTA, 2 CTAs/SM ----------------
__global__ __launch_bounds__(NT, 2)
void cyl_pers_kernel(const float* __restrict__ theta,
                     const float* __restrict__ xc,
                     const float* __restrict__ b1,
                     const float* __restrict__ b2,
                     const float* __restrict__ eta,
                     float* __restrict__ out,
                     int B, int ntiles)
{
    extern __shared__ char smem[];
    const uint32_t smb = smem_u32(smem);
    const int t = threadIdx.x;
    const int w = t >> 5;          // 0..7
    const int l = t & 31;

    // ---- one-time W1 + bias staging ----
    for (int i = t; i < NH * NFEAT / 2; i += NT) {
        int n = i >> 5, kp = i & 31;
        uint32_t off = SWZ128(n * 128 + kp * 4);
        *(uint32_t*)(smem + SM_W1H + off) = g_W1T_hi[i];
        *(uint32_t*)(smem + SM_W1L + off) = g_W1T_lo[i];
    }
    if (t < NH) ((float*)(smem + SM_B1))[t] = b1[t];
    if (t < NP) ((float*)(smem + SM_B2))[t] = b2[t];
    const float e0 = eta[0];

    // lane address components
    const uint32_t a512  = (uint32_t)((l & 15) * 512 + ((l >> 4) & 1) * 16);
    const uint32_t b128q = (uint32_t)(((l & 7) + ((l >> 4) & 1) * 8) * 128 + ((l >> 3) & 1) * 16);
    const int rq = l >> 2, cq = 2 * (l & 3);
    const int gq = l >> 2, tig = l & 3;

    // stage-1 mapping: 2 m-groups x 4 col-groups (64 cols each)
    const int cg = w & 3, mt = w >> 2;
    // stage-2 mapping: 2 mg x 4 ng (24 cols each), full K
    const int mg = w >> 2, ng = w & 3;

    const uint4* w2fp = g_W2F + (ng * 16 * 3 * 32) + l;
    const float2* xp = (const float2*)xc;
    float* pp = (float*)(smem + SM_PP);

    __syncthreads();

    const int stride = gridDim.x * TM;
    int it = 0;
    int last_row0 = 0;
    for (int tile = blockIdx.x; tile < ntiles; tile += gridDim.x, it++) {
        const int row0 = tile * TM;

        // ========== phase 1: stage 1 MMA (A direct from gmem) + epi1 + spline(prev) ==========
        {
            float P1[8][4], Q1[8][4];
            #pragma unroll
            for (int n = 0; n < 8; n++)
                #pragma unroll
                for (int q = 0; q < 4; q++) { P1[n][q] = 0.f; Q1[n][q] = 0.f; }

            // A-fragment source rows for this warp (m16n8k16 layout)
            const int r0i = row0 + mt * 16 + gq;
            const bool p0 = r0i < B, p1 = (r0i + 8) < B;
            const float2* xr0 = xp + (size_t)r0i * 32 + tig;
            const float2* xr1 = xp + (size_t)(r0i + 8) * 32 + tig;
            const float2 z2 = make_float2(0.f, 0.f);

            // software pipeline over kt
            float2 f0 = p0 ? xr0[0] : z2;
            float2 f1 = p1 ? xr1[0] : z2;
            float2 f2v = p0 ? xr0[4] : z2;
            float2 f3v = p1 ? xr1[4] : z2;

            #pragma unroll
            for (int kt = 0; kt < 4; kt++) {
                float2 n0, n1, n2v, n3v;
                if (kt < 3) {
                    n0  = p0 ? xr0[(kt + 1) * 8]     : z2;
                    n1  = p1 ? xr1[(kt + 1) * 8]     : z2;
                    n2v = p0 ? xr0[(kt + 1) * 8 + 4] : z2;
                    n3v = p1 ? xr1[(kt + 1) * 8 + 4] : z2;
                }
                uint32_t Ah[4], Al[4];
                Ah[0] = pack_hi(f0.x,  f0.y);  Al[0] = pack_lo(f0.x,  f0.y);
                Ah[1] = pack_hi(f1.x,  f1.y);  Al[1] = pack_lo(f1.x,  f1.y);
                Ah[2] = pack_hi(f2v.x, f2v.y); Al[2] = pack_lo(f2v.x, f2v.y);
                Ah[3] = pack_hi(f3v.x, f3v.y); Al[3] = pack_lo(f3v.x, f3v.y);

                #pragma unroll
                for (int np = 0; np < 4; np++) {
                    uint32_t Bh[4], Bl[4];
                    uint32_t ob = b128q + (uint32_t)((cg * 64 + np * 16) * 128 + kt * 32);
                    ldsm_x4(smb + SM_W1H + SWZ128(ob), Bh);
                    ldsm_x4(smb + SM_W1L + SWZ128(ob), Bl);
                    mma16816(P1[2*np],   Ah, Bh[0], Bh[1]);
                    mma16816(Q1[2*np],   Ah, Bl[0], Bl[1]);
                    mma16816(Q1[2*np],   Al, Bh[0], Bh[1]);
                    mma16816(P1[2*np+1], Ah, Bh[2], Bh[3]);
                    mma16816(Q1[2*np+1], Ah, Bl[2], Bl[3]);
                    mma16816(Q1[2*np+1], Al, Bh[2], Bh[3]);
                }
                f0 = n0; f1 = n1; f2v = n2v; f3v = n3v;
            }

            // epilogue 1: h = relu(C1 + b1) -> bf16 hi/lo smem (SWZ512)
            const float* b1s = (const float*)(smem + SM_B1);
            #pragma unroll
            for (int n = 0; n < 8; n++) {
                int col = cg * 64 + n * 8 + cq;
                float bb0 = b1s[col], bb1 = b1s[col + 1];
                int r0 = mt * 16 + rq;
                float v0 = fmaxf(P1[n][0] + Q1[n][0] + bb0, 0.f);
                float v1 = fmaxf(P1[n][1] + Q1[n][1] + bb1, 0.f);
                float v2 = fmaxf(P1[n][2] + Q1[n][2] + bb0, 0.f);
                float v3 = fmaxf(P1[n][3] + Q1[n][3] + bb1, 0.f);
                uint32_t o0 = SWZ512(r0 * 512 + col * 2);
                uint32_t o1 = SWZ512((r0 + 8) * 512 + col * 2);
                *(uint32_t*)(smem + SM_HH + o0) = pack_hi(v0, v1);
                *(uint32_t*)(smem + SM_HL + o0) = pack_lo(v0, v1);
                *(uint32_t*)(smem + SM_HH + o1) = pack_hi(v2, v3);
                *(uint32_t*)(smem + SM_HL + o1) = pack_lo(v2, v3);
            }
        }

        // spline of PREVIOUS tile (pp from last phase 2) — overlaps epi1/MMA tails
        if (it > 0)
            spline_rows4(pp, w, l, row0 - stride, theta, out, B);
        __syncthreads();   // 1: h visible; spline(prev) done (pp writable)

        // ========== phase 2: stage 2 MMA (W2F stream) + epi2 -> pp ==========
        {
            float P2[3][4], Q2[3][4];
            #pragma unroll
            for (int n = 0; n < 3; n++)
                #pragma unroll
                for (int q = 0; q < 4; q++) { P2[n][q] = 0.f; Q2[n][q] = 0.f; }

            uint4 bf[3];
            #pragma unroll
            for (int n = 0; n < 3; n++) bf[n] = w2fp[n * 32];

            #pragma unroll 4
            for (int k = 0; k < 16; k++) {
                uint4 bn[3];
                if (k < 15) {
                    #pragma unroll
                    for (int n = 0; n < 3; n++) bn[n] = w2fp[((k + 1) * 3 + n) * 32];
                }
                uint32_t Ah[4], Al[4];
                uint32_t oa = a512 + (uint32_t)(mg * 8192 + k * 32);
                ldsm_x4(smb + SM_HH + SWZ512(oa), Ah);
                ldsm_x4(smb + SM_HL + SWZ512(oa), Al);
                #pragma unroll
                for (int n = 0; n < 3; n++) {
                    mma16816(P2[n], Ah, bf[n].x, bf[n].y);
                    mma16816(Q2[n], Ah, bf[n].z, bf[n].w);
                    mma16816(Q2[n], Al, bf[n].x, bf[n].y);
                }
                #pragma unroll
                for (int n = 0; n < 3; n++) bf[n] = bn[n];
            }

            // epilogue 2 straight to pp (own buffer; protected by barrier 1)
            const float* b2s = (const float*)(smem + SM_B2);
            #pragma unroll
            for (int n = 0; n < 3; n++) {
                int col = ng * 24 + n * 8 + cq;
                float bb0 = b2s[col], bb1 = b2s[col + 1];
                int r0 = mg * 16 + rq;
                pp[r0 * PS + col]           = (P2[n][0] + Q2[n][0] + bb0) * e0;
                pp[r0 * PS + col + 1]       = (P2[n][1] + Q2[n][1] + bb1) * e0;
                pp[(r0 + 8) * PS + col]     = (P2[n][2] + Q2[n][2] + bb0) * e0;
                pp[(r0 + 8) * PS + col + 1] = (P2[n][3] + Q2[n][3] + bb1) * e0;
            }
        }
        __syncthreads();   // 2: pp complete; h consumed

        last_row0 = row0;
    }

    // ---- drain: spline of the final tile ----
    if (it > 0)
        spline_rows4(pp, w, l, last_row0, theta, out, B);
}

extern "C" void kernel_launch(void* const* d_in, const int* in_sizes, int n_in,
                              void* d_out, int out_size)
{
    const float* theta = (const float*)d_in[0];
    const float* xc    = (const float*)d_in[1];
    const float* W1    = (const float*)d_in[2];
    const float* b1    = (const float*)d_in[3];
    const float* W2    = (const float*)d_in[4];
    const float* b2    = (const float*)d_in[5];
    const float* eta   = (const float*)d_in[6];
    float* out = (float*)d_out;

    int B = in_sizes[0];

    static int nsm = 0;
    if (nsm == 0) {
        cudaDeviceProp prop;
        if (cudaGetDeviceProperties(&prop, 0) == cudaSuccess && prop.multiProcessorCount > 0)
            nsm = prop.multiProcessorCount;
        else
            nsm = 148;
        cudaFuncSetAttribute(cyl_pers_kernel, cudaFuncAttributeMaxDynamicSharedMemorySize, SM_TOTAL);
        cudaFuncSetAttribute(cyl_pers_kernel, cudaFuncAttributePreferredSharedMemoryCarveout,
                             cudaSharedmemCarveoutMaxShared);
    }

    int prep_elems = NH * NFEAT / 2 + 4 * 16 * 3 * 32;
    prep_kernel<<<(prep_elems + 255) / 256, 256>>>(W1, W2);

    int ntiles = (B + TM - 1) / TM;
    int grid = 2 * nsm;
    if (grid > ntiles) grid = ntiles;
    cyl_pers_kernel<<<grid, NT, SM_TOTAL>>>(theta, xc, b1, b2, eta, out, B, ntiles);
}

// round 17
// speedup vs baseline: 1.1058x; 1.1058x over previous
#include <cuda_runtime.h>
#include <cuda_bf16.h>
#include <math.h>
#include <stdint.h>

// ---------------- problem constants ----------------
#define NB     32
#define NFEAT  64
#define NH     256
#define NP     96
#define TM     32           // rows per tile (16 per 4-warp group)
#define NT     256          // 8 warps per CTA; 2 CTAs per SM
#define PS     100          // padded row stride (floats) for pp

#define TWO_PI_F   6.2831853071795864769f
#define MIN_WH     1e-3f
#define MIN_D      1e-3f
#define DERIV_OFF  0.5413248546129181f     // log(e-1)
#define SIZE_SCALE (1.0f - 1e-3f * 32.0f)

// ---- smem layout (bytes), per CTA = 105.4 KB -> 2 CTAs/SM ----
#define SM_W1H   0          // W1T hi [256 n][64 k bf16 = 128B rows, SWZ128]  32KB
#define SM_W1L   32768
#define SM_X     65536      // X: hi @0, lo @4096 (SWZ128)                     8KB
#define SM_HH    73728      // h hi [32 r][256 bf16, SWZ512]                  16KB
#define SM_HL    90112      // h lo                                           16KB
// pp: per-group buffer INSIDE the group's own h-hi half:
//   group g params f32[16][PS] at SM_HH + g*8192 (6400B <= 8192B half)
#define SM_B1    106496     // b1 f32[256]
#define SM_B2    107520     // b2 f32[96]
#define SM_TOTAL 107904

#define SWZ128(o) ((uint32_t)(o) ^ (((uint32_t)(o) >> 3) & 0x70u))
#define SWZ512(o) ((uint32_t)(o) ^ (((uint32_t)(o) >> 5) & 0x70u))

// group-scope named barrier (group g = threads g*128..g*128+127)
#define GBAR(g) asm volatile("bar.sync %0, 128;" :: "r"((g) + 1) : "memory")

// ---------------- pre-split weights (device globals) ----------------
__device__ uint32_t g_W1T_hi[NH * NFEAT / 2];   // [n][kpair]
__device__ uint32_t g_W1T_lo[NH * NFEAT / 2];
// W2 fragment-ordered: [ng(4)][k(16)][n(3)][lane(32)] -> uint4{bh0,bh1,bl0,bl1}
__device__ uint4 g_W2F[4 * 16 * 3 * 32];

// ---------------- helpers ----------------
static __device__ __forceinline__ uint32_t smem_u32(const void* p) {
    uint32_t a;
    asm("{ .reg .u64 t; cvta.to.shared.u64 t, %1; cvt.u32.u64 %0, t; }" : "=r"(a) : "l"(p));
    return a;
}
static __device__ __forceinline__ void ldsm_x4(uint32_t addr, uint32_t r[4]) {
    asm volatile("ldmatrix.sync.aligned.m8n8.x4.shared.b16 {%0,%1,%2,%3}, [%4];"
                 : "=r"(r[0]), "=r"(r[1]), "=r"(r[2]), "=r"(r[3]) : "r"(addr));
}
static __device__ __forceinline__ void mma16816(float c[4], const uint32_t a[4],
                                                uint32_t b0, uint32_t b1) {
    asm volatile("mma.sync.aligned.m16n8k16.row.col.f32.bf16.bf16.f32 "
                 "{%0,%1,%2,%3}, {%4,%5,%6,%7}, {%8,%9}, {%0,%1,%2,%3};"
                 : "+f"(c[0]), "+f"(c[1]), "+f"(c[2]), "+f"(c[3])
                 : "r"(a[0]), "r"(a[1]), "r"(a[2]), "r"(a[3]), "r"(b0), "r"(b1));
}
static __device__ __forceinline__ uint32_t pack_hi(float v0, float v1) {
    __nv_bfloat16 h0 = __float2bfloat16_rn(v0), h1 = __float2bfloat16_rn(v1);
    return (uint32_t)__bfloat16_as_ushort(h0) | ((uint32_t)__bfloat16_as_ushort(h1) << 16);
}
static __device__ __forceinline__ uint32_t pack_lo(float v0, float v1) {
    __nv_bfloat16 h0 = __float2bfloat16_rn(v0), h1 = __float2bfloat16_rn(v1);
    __nv_bfloat16 l0 = __float2bfloat16_rn(v0 - __bfloat162float(h0));
    __nv_bfloat16 l1 = __float2bfloat16_rn(v1 - __bfloat162float(h1));
    return (uint32_t)__bfloat16_as_ushort(l0) | ((uint32_t)__bfloat16_as_ushort(l1) << 16);
}
static __device__ __forceinline__ float softplus_f(float x) {
    return (x > 0.0f) ? (x + __logf(1.0f + __expf(-x))) : __logf(1.0f + __expf(x));
}

// 4-row interleaved circular RQ spline (lane = bin).
// ppg: group-local param buffer f32[16][PS]; local rows rl = wg + 4j;
// global row = rowbase + rl.
static __device__ __forceinline__ void spline_rows4(const float* ppg, int wg, int l,
                                                    int rowbase,
                                                    const float* __restrict__ theta,
                                                    float* __restrict__ out, int B)
{
    const unsigned FULL = 0xffffffffu;
    float uw[4], uh[4], ud[4], thv[4];
    int rowv[4];
    #pragma unroll
    for (int j = 0; j < 4; j++) {
        int rl = wg + 4 * j;
        int row = rowbase + rl;
        rowv[j] = row;
        thv[j] = (row < B) ? theta[row] : 0.f;
        uw[j] = ppg[rl * PS + l];
        uh[j] = ppg[rl * PS + NB + l];
        ud[j] = ppg[rl * PS + 2 * NB + l] + DERIV_OFF;
    }

    float cw[4], ch[4];
    #pragma unroll
    for (int j = 0; j < 4; j++) { cw[j] = __expf(uw[j]); ch[j] = __expf(uh[j]); }

    #pragma unroll
    for (int o = 1; o < 32; o <<= 1) {
        float aw[4], ah[4];
        #pragma unroll
        for (int j = 0; j < 4; j++) {
            aw[j] = __shfl_up_sync(FULL, cw[j], o);
            ah[j] = __shfl_up_sync(FULL, ch[j], o);
        }
        #pragma unroll
        for (int j = 0; j < 4; j++) {
            if (l >= o) { cw[j] += aw[j]; ch[j] += ah[j]; }
        }
    }

    float kw[4], kh[4], dsp[4];
    const float base = MIN_WH * (float)(l + 1);
    #pragma unroll
    for (int j = 0; j < 4; j++) {
        float rw = 1.0f / __shfl_sync(FULL, cw[j], 31);
        float rh = 1.0f / __shfl_sync(FULL, ch[j], 31);
        kw[j] = (l == 31) ? TWO_PI_F : TWO_PI_F * (base + SIZE_SCALE * cw[j] * rw);
        kh[j] = (l == 31) ? TWO_PI_F : TWO_PI_F * (base + SIZE_SCALE * ch[j] * rh);
        dsp[j] = MIN_D + softplus_f(ud[j]);
    }

    #pragma unroll
    for (int j = 0; j < 4; j++) {
        unsigned bal = __ballot_sync(FULL, thv[j] >= kw[j]);
        int bin = __popc(bal);
        if (bin > NB - 1) bin = NB - 1;
        int lo = (bin > 0) ? bin - 1 : 0;

        float cw_hi = __shfl_sync(FULL, kw[j], bin);
        float cw_lo = __shfl_sync(FULL, kw[j], lo);
        float ch_hi = __shfl_sync(FULL, kh[j], bin);
        float ch_lo = __shfl_sync(FULL, kh[j], lo);
        float d_k   = __shfl_sync(FULL, dsp[j], bin);
        float d_k1  = __shfl_sync(FULL, dsp[j], (bin + 1) & 31);
        if (bin == 0) { cw_lo = 0.0f; ch_lo = 0.0f; }

        float in_w = cw_hi - cw_lo;
        float in_h = ch_hi - ch_lo;

        float delta = in_h / in_w;
        float th    = (thv[j] - cw_lo) / in_w;
        float om    = th * (1.0f - th);
        float den   = delta + (d_k1 + d_k - 2.0f * delta) * om;
        float num   = in_h * (delta * th * th + d_k * om);
        float outv  = ch_lo + num / den;

        float omt = 1.0f - th;
        float dn  = delta * delta * (d_k1 * th * th + 2.0f * delta * om + d_k * omt * omt);
        float lad = __logf(dn) - 2.0f * __logf(den);

        if (l == 0 && rowv[j] < B) {
            out[rowv[j]]     = outv;
            out[B + rowv[j]] = lad;
        }
    }
}

// ---------------- prep: W1T hi/lo pairs + W2 fragment-ordered uint4 ----------------
__global__ void prep_kernel(const float* __restrict__ W1, const float* __restrict__ W2)
{
    int i = blockIdx.x * blockDim.x + threadIdx.x;
    if (i < NH * NFEAT / 2) {                      // W1 [64][256] -> W1T[n][kpair]
        int n = i >> 5, kp = i & 31;
        float w0 = W1[(2 * kp)     * NH + n];
        float w1 = W1[(2 * kp + 1) * NH + n];
        g_W1T_hi[i] = pack_hi(w0, w1);
        g_W1T_lo[i] = pack_lo(w0, w1);
    }
    int j = i - NH * NFEAT / 2;
    if (j >= 0 && j < 4 * 16 * 3 * 32) {           // W2F fragment layout
        int ng   = j / (16 * 3 * 32);
        int rem  = j - ng * (16 * 3 * 32);
        int k    = rem / (3 * 32);
        int n    = (rem / 32) % 3;
        int lane = rem & 31;

        int n2  = ng * 24 + n * 8 + (lane >> 2);
        int kp0 = k * 8 + (lane & 3);
        int kp1 = kp0 + 4;
        float a0 = W2[(2 * kp0)     * NP + n2];
        float a1 = W2[(2 * kp0 + 1) * NP + n2];
        float b0 = W2[(2 * kp1)     * NP + n2];
        float b1 = W2[(2 * kp1 + 1) * NP + n2];
        uint4 v;
        v.x = pack_hi(a0, a1);
        v.y = pack_hi(b0, b1);
        v.z = pack_lo(a0, a1);
        v.w = pack_lo(b0, b1);
        g_W2F[j] = v;
    }
}

// ---------------- persistent fused kernel: 2 decoupled 4-warp groups/CTA ----------------
__global__ __launch_bounds__(NT, 2)
void cyl_pers_kernel(const float* __restrict__ theta,
                     const float* __restrict__ xc,
                     const float* __restrict__ b1,
                     const float* __restrict__ b2,
                     const float* __restrict__ eta,
                     float* __restrict__ out,
                     int B, int ntiles)
{
    extern __shared__ char smem[];
    const uint32_t smb = smem_u32(smem);
    const int t = threadIdx.x;
    const int w = t >> 5;          // 0..7
    const int l = t & 31;
    const int g  = w >> 2;         // group 0/1 (4 warps, 128 threads)
    const int wg = w & 3;          // warp in group
    const int tg = t & 127;        // thread in group

    // ---- one-time W1 + bias staging ----
    for (int i = t; i < NH * NFEAT / 2; i += NT) {
        int n = i >> 5, kp = i & 31;
        uint32_t off = SWZ128(n * 128 + kp * 4);
        *(uint32_t*)(smem + SM_W1H + off) = g_W1T_hi[i];
        *(uint32_t*)(smem + SM_W1L + off) = g_W1T_lo[i];
    }
    if (t < NH) ((float*)(smem + SM_B1))[t] = b1[t];
    if (t < NP) ((float*)(smem + SM_B2))[t] = b2[t];
    const float e0 = eta[0];

    // lane address components
    const uint32_t a128  = (uint32_t)((l & 15) * 128 + ((l >> 4) & 1) * 16);
    const uint32_t a512  = (uint32_t)((l & 15) * 512 + ((l >> 4) & 1) * 16);
    const uint32_t b128q = (uint32_t)(((l & 7) + ((l >> 4) & 1) * 8) * 128 + ((l >> 3) & 1) * 16);
    const int rq = l >> 2, cq = 2 * (l & 3);

    // stage-1: warp (g, cg=wg): A rows g*16..+16, cols wg*64..+64
    // stage-2: warp (g, ng=wg): h rows g*16..+16, cols wg*24..+24
    const int cg = wg, ng = wg;

    const uint4* w2fp = g_W2F + (ng * 16 * 3 * 32) + l;
    const float2* xp = (const float2*)xc;
    float* ppg = (float*)(smem + SM_HH + g * 8192);   // group-local pp (inside own h-hi half)

    // ---- pre-loop: each group stages its own X half ----
    {
        int tile0 = blockIdx.x;
        #pragma unroll
        for (int j = 0; j < 4; j++) {
            int i = tg + j * 128;            // 512 float2 per group half
            int r = g * 16 + (i >> 5), kp = i & 31;
            int row = tile0 * TM + r;
            float2 v = (row < B) ? xp[row * 32 + kp] : make_float2(0.f, 0.f);
            uint32_t off = SWZ128(r * 128 + kp * 4);
            *(uint32_t*)(smem + SM_X + off)        = pack_hi(v.x, v.y);
            *(uint32_t*)(smem + SM_X + 4096 + off) = pack_lo(v.x, v.y);
        }
    }
    __syncthreads();

    for (int tile = blockIdx.x; tile < ntiles; tile += gridDim.x) {
        const int row0 = tile * TM;
        const int ntile = tile + gridDim.x;
        const bool have_next = ntile < ntiles;

        // hoisted prefetches: next-X (own half) + first W2F fragments
        float2 xv[4];
        if (have_next) {
            #pragma unroll
            for (int j = 0; j < 4; j++) {
                int i = tg + j * 128;
                int r = g * 16 + (i >> 5), kp = i & 31;
                int row = ntile * TM + r;
                xv[j] = (row < B) ? xp[row * 32 + kp] : make_float2(0.f, 0.f);
            }
        }
        uint4 bf[3];
        #pragma unroll
        for (int n = 0; n < 3; n++) bf[n] = w2fp[n * 32];

        // ========== phase 1: stage 1 MMA + epi1 -> h (own half) ==========
        {
            float P1[8][4], Q1[8][4];
            #pragma unroll
            for (int n = 0; n < 8; n++)
                #pragma unroll
                for (int q = 0; q < 4; q++) { P1[n][q] = 0.f; Q1[n][q] = 0.f; }

            #pragma unroll
            for (int k = 0; k < 4; k++) {
                uint32_t Ah[4], Al[4];
                uint32_t o = a128 + (uint32_t)(g * 2048 + k * 32);
                ldsm_x4(smb + SM_X +        SWZ128(o), Ah);
                ldsm_x4(smb + SM_X + 4096 + SWZ128(o), Al);
                #pragma unroll
                for (int np = 0; np < 4; np++) {
                    uint32_t Bh[4], Bl[4];
                    uint32_t ob = b128q + (uint32_t)((cg * 64 + np * 16) * 128 + k * 32);
                    ldsm_x4(smb + SM_W1H + SWZ128(ob), Bh);
                    ldsm_x4(smb + SM_W1L + SWZ128(ob), Bl);
                    mma16816(P1[2*np],   Ah, Bh[0], Bh[1]);
                    mma16816(Q1[2*np],   Ah, Bl[0], Bl[1]);
                    mma16816(Q1[2*np],   Al, Bh[0], Bh[1]);
                    mma16816(P1[2*np+1], Ah, Bh[2], Bh[3]);
                    mma16816(Q1[2*np+1], Ah, Bl[2], Bl[3]);
                    mma16816(Q1[2*np+1], Al, Bh[2], Bh[3]);
                }
            }

            const float* b1s = (const float*)(smem + SM_B1);
            #pragma unroll
            for (int n = 0; n < 8; n++) {
                int col = cg * 64 + n * 8 + cq;
                float bb0 = b1s[col], bb1 = b1s[col + 1];
                int r0 = g * 16 + rq;
                float v0 = fmaxf(P1[n][0] + Q1[n][0] + bb0, 0.f);
                float v1 = fmaxf(P1[n][1] + Q1[n][1] + bb1, 0.f);
                float v2 = fmaxf(P1[n][2] + Q1[n][2] + bb0, 0.f);
                float v3 = fmaxf(P1[n][3] + Q1[n][3] + bb1, 0.f);
                uint32_t o0 = SWZ512(r0 * 512 + col * 2);
                uint32_t o1 = SWZ512((r0 + 8) * 512 + col * 2);
                *(uint32_t*)(smem + SM_HH + o0) = pack_hi(v0, v1);
                *(uint32_t*)(smem + SM_HL + o0) = pack_lo(v0, v1);
                *(uint32_t*)(smem + SM_HH + o1) = pack_hi(v2, v3);
                *(uint32_t*)(smem + SM_HL + o1) = pack_lo(v2, v3);
            }
        }
        GBAR(g);   // 1: own h half visible

        // ========== phase 2: stage 2 MMA (W2F stream) + next-X STS ==========
        float P2[3][4], Q2[3][4];
        {
            #pragma unroll
            for (int n = 0; n < 3; n++)
                #pragma unroll
                for (int q = 0; q < 4; q++) { P2[n][q] = 0.f; Q2[n][q] = 0.f; }

            #pragma unroll 4
            for (int k = 0; k < 16; k++) {
                uint4 bn[3];
                if (k < 15) {
                    #pragma unroll
                    for (int n = 0; n < 3; n++) bn[n] = w2fp[((k + 1) * 3 + n) * 32];
                }
                uint32_t Ah[4], Al[4];
                uint32_t oa = a512 + (uint32_t)(g * 8192 + k * 32);
                ldsm_x4(smb + SM_HH + SWZ512(oa), Ah);
                ldsm_x4(smb + SM_HL + SWZ512(oa), Al);
                #pragma unroll
                for (int n = 0; n < 3; n++) {
                    mma16816(P2[n], Ah, bf[n].x, bf[n].y);
                    mma16816(Q2[n], Ah, bf[n].z, bf[n].w);
                    mma16816(Q2[n], Al, bf[n].x, bf[n].y);
                }
                #pragma unroll
                for (int n = 0; n < 3; n++) bf[n] = bn[n];
            }

            if (have_next) {
                #pragma unroll
                for (int j = 0; j < 4; j++) {
                    int i = tg + j * 128;
                    int r = g * 16 + (i >> 5), kp = i & 31;
                    uint32_t off = SWZ128(r * 128 + kp * 4);
                    *(uint32_t*)(smem + SM_X + off)        = pack_hi(xv[j].x, xv[j].y);
                    *(uint32_t*)(smem + SM_X + 4096 + off) = pack_lo(xv[j].x, xv[j].y);
                }
            }
        }
        GBAR(g);   // 2: group's h reads done -> ppg region writable; X staged

        // ========== phase 3: epilogue 2 -> ppg ==========
        {
            const float* b2s = (const float*)(smem + SM_B2);
            #pragma unroll
            for (int n = 0; n < 3; n++) {
                int col = ng * 24 + n * 8 + cq;
                float bb0 = b2s[col], bb1 = b2s[col + 1];
                ppg[rq * PS + col]           = (P2[n][0] + Q2[n][0] + bb0) * e0;
                ppg[rq * PS + col + 1]       = (P2[n][1] + Q2[n][1] + bb1) * e0;
                ppg[(rq + 8) * PS + col]     = (P2[n][2] + Q2[n][2] + bb0) * e0;
                ppg[(rq + 8) * PS + col + 1] = (P2[n][3] + Q2[n][3] + bb1) * e0;
            }
        }
        GBAR(g);   // 3: ppg ready

        // ========== phase 4: spline (4 warps x 4 rows of own half) ==========
        spline_rows4(ppg, wg, l, row0 + g * 16, theta, out, B);
        GBAR(g);   // 4: ppg reads done before next epi1 overwrites h half
    }
}

extern "C" void kernel_launch(void* const* d_in, const int* in_sizes, int n_in,
                              void* d_out, int out_size)
{
    const float* theta = (const float*)d_in[0];
    const float* xc    = (const float*)d_in[1];
    const float* W1    = (const float*)d_in[2];
    const float* b1    = (const float*)d_in[3];
    const float* W2    = (const float*)d_in[4];
    const float* b2    = (const float*)d_in[5];
    const float* eta   = (const float*)d_in[6];
    float* out = (float*)d_out;

    int B = in_sizes[0];

    static int nsm = 0;
    if (nsm == 0) {
        cudaDeviceProp prop;
        if (cudaGetDeviceProperties(&prop, 0) == cudaSuccess && prop.multiProcessorCount > 0)
            nsm = prop.multiProcessorCount;
        else
            nsm = 148;
        cudaFuncSetAttribute(cyl_pers_kernel, cudaFuncAttributeMaxDynamicSharedMemorySize, SM_TOTAL);
        cudaFuncSetAttribute(cyl_pers_kernel, cudaFuncAttributePreferredSharedMemoryCarveout,
                             cudaSharedmemCarveoutMaxShared);
    }

    int prep_elems = NH * NFEAT / 2 + 4 * 16 * 3 * 32;
    prep_kernel<<<(prep_elems + 255) / 256, 256>>>(W1, W2);

    int ntiles = (B + TM - 1) / TM;
    int grid = 2 * nsm;
    if (grid > ntiles) grid = ntiles;
    cyl_pers_kernel<<<grid, NT, SM_TOTAL>>>(theta, xc, b1, b2, eta, out, B, ntiles);
}